// round 7
// baseline (speedup 1.0000x reference)
#include <cuda_runtime.h>
#include <cuda_bf16.h>

// Problem constants (fixed by the dataset)
#define Bn 4
#define Nn 50000
#define Dn 256
#define En 800000
#define NPTS (Bn * Nn)   // 200000
#define MAXDEG 96        // Poisson(32): P(deg>96) ~ 1e-18 over 50k nodes

// Predict grid: 5000 warps x 40 points each = 200000 exactly (no bounds checks)
#define PRED_BLOCKS 625
#define PRED_WARPS  (PRED_BLOCKS * 8)   // 5000

// XPBD state, batch-interleaved: g_x[buf][4*n + b] = float4(x,y,z,pad).
// The 4 batches of a node are 64B contiguous: sibling threads (n,0..3)
// gather a neighbor with one fully-used 64B segment.
__device__ float4 g_x[2][NPTS];

// Fixed-slot incidence table: node n owns g_slot[n*MAXDEG .. n*MAXDEG+deg).
// entry = {4*neighbor (pre-scaled float4 index), bitcast(L0)}. Rows padded to
// a multiple of 4 with self-edges (zero contribution: dx=dy=dz=0).
__device__ int  g_cnt[Nn];
__device__ int2 g_slot[Nn * MAXDEG];   // 38.4 MB

// ---------------------------------------------------------------------------
// Stage 1: x_pred = keypoints + tau * (hand_tokens @ head_w + head_b)
// Warp-persistent weights in REGISTERS (no smem in the hot loop -> no bank
// conflicts). Lane l owns cols 4l..4l+3 and 128+4l..128+4l+3 (24 weights =
// 6 float4 loads, once per warp). Each warp sweeps 40 points, 2 per
// iteration for MLP; per point: 2 coalesced LDG.128 + 24 FMA + shfl-reduce.
// ---------------------------------------------------------------------------
__global__ __launch_bounds__(256) void predict_kernel(
    const float* __restrict__ kp, const float* __restrict__ ts,
    const float* __restrict__ ht, const float* __restrict__ hw,
    const float* __restrict__ hb)
{
    int lane = threadIdx.x & 31;
    int w    = (blockIdx.x * blockDim.x + threadIdx.x) >> 5;   // 0..4999

    // Weight registers: rows 4l..4l+3 (block A) and 128+4l.. (block B).
    // hw is row-major (D,3): rows 4l..4l+3 = 12 consecutive floats = 3 float4.
    const float4* hw4 = reinterpret_cast<const float4*>(hw);
    float4 qa0 = __ldg(&hw4[3 * lane + 0]);
    float4 qa1 = __ldg(&hw4[3 * lane + 1]);
    float4 qa2 = __ldg(&hw4[3 * lane + 2]);
    float4 qb0 = __ldg(&hw4[96 + 3 * lane + 0]);
    float4 qb1 = __ldg(&hw4[96 + 3 * lane + 1]);
    float4 qb2 = __ldg(&hw4[96 + 3 * lane + 2]);
    float bb0 = __ldg(&hb[0]), bb1 = __ldg(&hb[1]), bb2 = __ldg(&hb[2]);

    const float4* ht4 = reinterpret_cast<const float4*>(ht);

#pragma unroll 1
    for (int it = 0; it < 20; it++) {
        int p0 = w + (2 * it + 0) * PRED_WARPS;
        int p1 = w + (2 * it + 1) * PRED_WARPS;

        // 4 independent 128-bit loads in flight
        float4 u0 = __ldg(&ht4[(size_t)p0 * 64 + lane]);
        float4 u1 = __ldg(&ht4[(size_t)p0 * 64 + 32 + lane]);
        float4 v0 = __ldg(&ht4[(size_t)p1 * 64 + lane]);
        float4 v1 = __ldg(&ht4[(size_t)p1 * 64 + 32 + lane]);

        float x0, y0, z0, x1, y1, z1;
        {
            x0 = u0.x * qa0.x;            y0 = u0.x * qa0.y;            z0 = u0.x * qa0.z;
            x0 = fmaf(u0.y, qa0.w, x0);   y0 = fmaf(u0.y, qa1.x, y0);   z0 = fmaf(u0.y, qa1.y, z0);
            x0 = fmaf(u0.z, qa1.z, x0);   y0 = fmaf(u0.z, qa1.w, y0);   z0 = fmaf(u0.z, qa2.x, z0);
            x0 = fmaf(u0.w, qa2.y, x0);   y0 = fmaf(u0.w, qa2.z, y0);   z0 = fmaf(u0.w, qa2.w, z0);
            x0 = fmaf(u1.x, qb0.x, x0);   y0 = fmaf(u1.x, qb0.y, y0);   z0 = fmaf(u1.x, qb0.z, z0);
            x0 = fmaf(u1.y, qb0.w, x0);   y0 = fmaf(u1.y, qb1.x, y0);   z0 = fmaf(u1.y, qb1.y, z0);
            x0 = fmaf(u1.z, qb1.z, x0);   y0 = fmaf(u1.z, qb1.w, y0);   z0 = fmaf(u1.z, qb2.x, z0);
            x0 = fmaf(u1.w, qb2.y, x0);   y0 = fmaf(u1.w, qb2.z, y0);   z0 = fmaf(u1.w, qb2.w, z0);

            x1 = v0.x * qa0.x;            y1 = v0.x * qa0.y;            z1 = v0.x * qa0.z;
            x1 = fmaf(v0.y, qa0.w, x1);   y1 = fmaf(v0.y, qa1.x, y1);   z1 = fmaf(v0.y, qa1.y, z1);
            x1 = fmaf(v0.z, qa1.z, x1);   y1 = fmaf(v0.z, qa1.w, y1);   z1 = fmaf(v0.z, qa2.x, z1);
            x1 = fmaf(v0.w, qa2.y, x1);   y1 = fmaf(v0.w, qa2.z, y1);   z1 = fmaf(v0.w, qa2.w, z1);
            x1 = fmaf(v1.x, qb0.x, x1);   y1 = fmaf(v1.x, qb0.y, y1);   z1 = fmaf(v1.x, qb0.z, z1);
            x1 = fmaf(v1.y, qb0.w, x1);   y1 = fmaf(v1.y, qb1.x, y1);   z1 = fmaf(v1.y, qb1.y, z1);
            x1 = fmaf(v1.z, qb1.z, x1);   y1 = fmaf(v1.z, qb1.w, y1);   z1 = fmaf(v1.z, qb2.x, z1);
            x1 = fmaf(v1.w, qb2.y, x1);   y1 = fmaf(v1.w, qb2.z, y1);   z1 = fmaf(v1.w, qb2.w, z1);
        }
#pragma unroll
        for (int o = 16; o >= 1; o >>= 1) {
            x0 += __shfl_xor_sync(0xffffffffu, x0, o);
            y0 += __shfl_xor_sync(0xffffffffu, y0, o);
            z0 += __shfl_xor_sync(0xffffffffu, z0, o);
            x1 += __shfl_xor_sync(0xffffffffu, x1, o);
            y1 += __shfl_xor_sync(0xffffffffu, y1, o);
            z1 += __shfl_xor_sync(0xffffffffu, z1, o);
        }
        if (lane == 0) {
            int b0i = p0 / Nn, n0 = p0 - b0i * Nn;
            float tau0 = fmaxf(1.0f - __ldg(&ts[b0i]), 0.001f);
            g_x[0][4 * n0 + b0i] = make_float4(
                fmaf(tau0, x0 + bb0, __ldg(&kp[(size_t)p0 * 3 + 0])),
                fmaf(tau0, y0 + bb1, __ldg(&kp[(size_t)p0 * 3 + 1])),
                fmaf(tau0, z0 + bb2, __ldg(&kp[(size_t)p0 * 3 + 2])), 0.0f);
            int b1i = p1 / Nn, n1 = p1 - b1i * Nn;
            float tau1 = fmaxf(1.0f - __ldg(&ts[b1i]), 0.001f);
            g_x[0][4 * n1 + b1i] = make_float4(
                fmaf(tau1, x1 + bb0, __ldg(&kp[(size_t)p1 * 3 + 0])),
                fmaf(tau1, y1 + bb1, __ldg(&kp[(size_t)p1 * 3 + 1])),
                fmaf(tau1, z1 + bb2, __ldg(&kp[(size_t)p1 * 3 + 2])), 0.0f);
        }
    }
}

// ---------------------------------------------------------------------------
// Incidence build (side stream, hidden under predict):
// zero cursors -> edge-parallel slotted fill -> pad rows to multiple of 4.
// ---------------------------------------------------------------------------
__global__ __launch_bounds__(256) void zero_kernel()
{
    int i = blockIdx.x * blockDim.x + threadIdx.x;
    if (i < Nn) g_cnt[i] = 0;
}

__global__ __launch_bounds__(256) void fill_kernel(
    const int* __restrict__ ei, const float* __restrict__ rest)
{
    int e = blockIdx.x * blockDim.x + threadIdx.x;
    if (e >= En) return;
    int s  = __ldg(&ei[e]);
    int d  = __ldg(&ei[En + e]);
    int L0 = __float_as_int(__ldg(&rest[e]));
    int cs = atomicAdd(&g_cnt[s], 1);
    if (cs < MAXDEG) g_slot[s * MAXDEG + cs] = make_int2(4 * d, L0);
    int cd = atomicAdd(&g_cnt[d], 1);
    if (cd < MAXDEG) g_slot[d * MAXDEG + cd] = make_int2(4 * s, L0);
}

__global__ __launch_bounds__(256) void pad_kernel()
{
    int n = blockIdx.x * blockDim.x + threadIdx.x;
    if (n >= Nn) return;
    int c = min(g_cnt[n], MAXDEG);
    int p = (c + 3) & ~3;                    // pad to multiple of 4
    int2 self = make_int2(4 * n, __float_as_int(1.0f));  // zero contribution
    for (int k = c; k < p; k++) g_slot[n * MAXDEG + k] = self;
    g_cnt[n] = p;
}

// ---------------------------------------------------------------------------
// One XPBD Jacobi iteration. Thread per (node, batch): no atomics, no copy,
// no tail masking (rows 4-padded). Neighbor indices pre-scaled by 4; the x0.5
// of the correction is deferred out of the loop (clamp at +-0.3, halve once).
// ---------------------------------------------------------------------------
__global__ __launch_bounds__(128) void node_kernel(int from, int to)
{
    int t = blockIdx.x * blockDim.x + threadIdx.x;
    if (t >= NPTS) return;
    int n = t >> 2;
    int b = t & 3;

    const float4* __restrict__ xin = g_x[from];
    float4 own = __ldg(&xin[t]);

    int deg = __ldg(&g_cnt[n]);              // multiple of 4
    const int2* row = &g_slot[n * MAXDEG];

    float ax = 0.f, ay = 0.f, az = 0.f;

    for (int k = 0; k < deg; k += 4) {
        int4 ea = __ldg(reinterpret_cast<const int4*>(row + k));
        int4 eb = __ldg(reinterpret_cast<const int4*>(row + k + 2));
        int   js[4]  = {ea.x, ea.z, eb.x, eb.z};    // already 4*j
        float L0s[4] = {__int_as_float(ea.y), __int_as_float(ea.w),
                        __int_as_float(eb.y), __int_as_float(eb.w)};
        float4 xj[4];
#pragma unroll
        for (int i = 0; i < 4; i++)
            xj[i] = __ldg(&xin[js[i] + b]);
#pragma unroll
        for (int i = 0; i < 4; i++) {
            float dx = own.x - xj[i].x;
            float dy = own.y - xj[i].y;
            float dz = own.z - xj[i].z;
            float d2 = fmaf(dx, dx, fmaf(dy, dy, dz * dz));
            float r  = rsqrtf(fmaxf(d2, 1e-24f));
            float f  = fmaf(L0s[i], r, -1.0f);       // 2x the true scale
            ax += fminf(fmaxf(f * dx, -0.3f), 0.3f);
            ay += fminf(fmaxf(f * dy, -0.3f), 0.3f);
            az += fminf(fmaxf(f * dz, -0.3f), 0.3f);
        }
    }

    g_x[to][t] = make_float4(fmaf(0.5f, ax, own.x),
                             fmaf(0.5f, ay, own.y),
                             fmaf(0.5f, az, own.z), 0.0f);
}

// ---------------------------------------------------------------------------
// Stage 3: v_eff = (x_corrected - keypoints) / tau
// ---------------------------------------------------------------------------
__global__ __launch_bounds__(256) void final_kernel(
    const float* __restrict__ kp, const float* __restrict__ ts,
    int buf, float* __restrict__ out)
{
    int n = blockIdx.x * blockDim.x + threadIdx.x;
    if (n >= Nn) return;
    const float4* x = g_x[buf];
#pragma unroll
    for (int b = 0; b < Bn; b++) {
        float4 p = x[4 * n + b];
        float inv_tau = 1.0f / fmaxf(1.0f - __ldg(&ts[b]), 0.001f);
        size_t o = (size_t)(b * Nn + n) * 3;
        out[o + 0] = (p.x - __ldg(&kp[o + 0])) * inv_tau;
        out[o + 1] = (p.y - __ldg(&kp[o + 1])) * inv_tau;
        out[o + 2] = (p.z - __ldg(&kp[o + 2])) * inv_tau;
    }
}

extern "C" void kernel_launch(void* const* d_in, const int* in_sizes, int n_in,
                              void* d_out, int out_size)
{
    const float* kp   = (const float*)d_in[0];  // keypoints   (B,N,3)
    const float* ts   = (const float*)d_in[1];  // timesteps   (B,)
    const float* ht   = (const float*)d_in[2];  // hand_tokens (B,N,D)
    const float* hw   = (const float*)d_in[3];  // head_w      (D,3)
    const float* hb   = (const float*)d_in[4];  // head_b      (3,)
    const int*   ei   = (const int*)  d_in[5];  // edge_index  (2,E)
    const float* rest = (const float*)d_in[6];  // rest_lengths(E,)
    float*       out  = (float*)d_out;          // v_eff       (B,N,3)

    (void)in_sizes; (void)n_in; (void)out_size;

    // Side stream + fork/join events, created once on the first (uncaptured)
    // correctness call. Host-side objects only.
    static cudaStream_t side = nullptr;
    static cudaEvent_t  ev_fork = nullptr, ev_join = nullptr;
    if (side == nullptr) {
        cudaStreamCreateWithFlags(&side, cudaStreamNonBlocking);
        cudaEventCreateWithFlags(&ev_fork, cudaEventDisableTiming);
        cudaEventCreateWithFlags(&ev_join, cudaEventDisableTiming);
    }

    const int nb_nodes = (Nn + 255) / 256;
    const int nb_edges = (En + 255) / 256;
    const int nb_nodeb = (NPTS + 127) / 128;

    // Fork: incidence build on side stream (LTS/atomic-bound), concurrent
    // with the DRAM-bound predict.
    cudaEventRecord(ev_fork, 0);
    cudaStreamWaitEvent(side, ev_fork, 0);
    zero_kernel<<<nb_nodes, 256, 0, side>>>();
    fill_kernel<<<nb_edges, 256, 0, side>>>(ei, rest);
    pad_kernel <<<nb_nodes, 256, 0, side>>>();

    // Stage 1 on the main stream, overlapping the build
    predict_kernel<<<PRED_BLOCKS, 256>>>(kp, ts, ht, hw, hb);

    // Join
    cudaEventRecord(ev_join, side);
    cudaStreamWaitEvent(0, ev_join, 0);

    // Stage 2: 4 Jacobi XPBD iterations, node-centric, ping-pong
    node_kernel<<<nb_nodeb, 128>>>(0, 1);
    node_kernel<<<nb_nodeb, 128>>>(1, 0);
    node_kernel<<<nb_nodeb, 128>>>(0, 1);
    node_kernel<<<nb_nodeb, 128>>>(1, 0);

    // Stage 3: velocity output from buffer 0
    final_kernel<<<nb_nodes, 256>>>(kp, ts, 0, out);
}

// round 8
// speedup vs baseline: 1.0599x; 1.0599x over previous
#include <cuda_runtime.h>
#include <cuda_bf16.h>

// Problem constants (fixed by the dataset)
#define Bn 4
#define Nn 50000
#define Dn 256
#define En 800000
#define NPTS (Bn * Nn)   // 200000
#define MAXDEG 96        // Poisson(32): P(deg>96) ~ 1e-18 over 50k nodes

// Predict grid: 5000 warps x 40 points each = 200000 exactly
#define PRED_BLOCKS 625
#define PRED_WARPS  (PRED_BLOCKS * 8)   // 5000

// XPBD state, batch-interleaved: g_x[buf][4*n + b] = float4(x,y,z,pad).
// The 4 batches of a node are 64B contiguous.
__device__ float4 g_x[2][NPTS];

// Fixed-slot incidence table: node n owns g_slot[n*MAXDEG .. n*MAXDEG+deg).
// entry = {4*neighbor (pre-scaled float4 index), bitcast(L0)}. Rows padded to
// a multiple of 4 with self-edges (zero contribution).
__device__ int  g_cnt[Nn];
__device__ int2 g_slot[Nn * MAXDEG];   // 38.4 MB

// ---------------------------------------------------------------------------
// Stage 1: x_pred = keypoints + tau * (hand_tokens @ head_w + head_b)
// Warp-persistent weights in registers; 4 points per iteration -> 8
// independent LDG.128 in flight per warp (crosses the DRAM latency-hiding
// threshold at ~25 warps/SM). Shfl-reduce 12 values at the end of each iter.
// ---------------------------------------------------------------------------
__global__ __launch_bounds__(256) void predict_kernel(
    const float* __restrict__ kp, const float* __restrict__ ts,
    const float* __restrict__ ht, const float* __restrict__ hw,
    const float* __restrict__ hb)
{
    int lane = threadIdx.x & 31;
    int w    = (blockIdx.x * blockDim.x + threadIdx.x) >> 5;   // 0..4999

    const float4* hw4 = reinterpret_cast<const float4*>(hw);
    float4 qa0 = __ldg(&hw4[3 * lane + 0]);
    float4 qa1 = __ldg(&hw4[3 * lane + 1]);
    float4 qa2 = __ldg(&hw4[3 * lane + 2]);
    float4 qb0 = __ldg(&hw4[96 + 3 * lane + 0]);
    float4 qb1 = __ldg(&hw4[96 + 3 * lane + 1]);
    float4 qb2 = __ldg(&hw4[96 + 3 * lane + 2]);
    float bb0 = __ldg(&hb[0]), bb1 = __ldg(&hb[1]), bb2 = __ldg(&hb[2]);

    const float4* ht4 = reinterpret_cast<const float4*>(ht);

#pragma unroll 1
    for (int it = 0; it < 10; it++) {
        int p[4];
        float4 u[4], u2[4];
#pragma unroll
        for (int i = 0; i < 4; i++) {
            p[i]  = w + (4 * it + i) * PRED_WARPS;
            u[i]  = __ldg(&ht4[(size_t)p[i] * 64 + lane]);
            u2[i] = __ldg(&ht4[(size_t)p[i] * 64 + 32 + lane]);
        }

        float X[4], Y[4], Z[4];
#pragma unroll
        for (int i = 0; i < 4; i++) {
            float x, y, z;
            x = u[i].x * qa0.x;            y = u[i].x * qa0.y;            z = u[i].x * qa0.z;
            x = fmaf(u[i].y, qa0.w, x);    y = fmaf(u[i].y, qa1.x, y);    z = fmaf(u[i].y, qa1.y, z);
            x = fmaf(u[i].z, qa1.z, x);    y = fmaf(u[i].z, qa1.w, y);    z = fmaf(u[i].z, qa2.x, z);
            x = fmaf(u[i].w, qa2.y, x);    y = fmaf(u[i].w, qa2.z, y);    z = fmaf(u[i].w, qa2.w, z);
            x = fmaf(u2[i].x, qb0.x, x);   y = fmaf(u2[i].x, qb0.y, y);   z = fmaf(u2[i].x, qb0.z, z);
            x = fmaf(u2[i].y, qb0.w, x);   y = fmaf(u2[i].y, qb1.x, y);   z = fmaf(u2[i].y, qb1.y, z);
            x = fmaf(u2[i].z, qb1.z, x);   y = fmaf(u2[i].z, qb1.w, y);   z = fmaf(u2[i].z, qb2.x, z);
            x = fmaf(u2[i].w, qb2.y, x);   y = fmaf(u2[i].w, qb2.z, y);   z = fmaf(u2[i].w, qb2.w, z);
            X[i] = x; Y[i] = y; Z[i] = z;
        }
#pragma unroll
        for (int o = 16; o >= 1; o >>= 1) {
#pragma unroll
            for (int i = 0; i < 4; i++) {
                X[i] += __shfl_xor_sync(0xffffffffu, X[i], o);
                Y[i] += __shfl_xor_sync(0xffffffffu, Y[i], o);
                Z[i] += __shfl_xor_sync(0xffffffffu, Z[i], o);
            }
        }
        if (lane == 0) {
#pragma unroll
            for (int i = 0; i < 4; i++) {
                int bi = p[i] / Nn, ni = p[i] - bi * Nn;
                float tau = fmaxf(1.0f - __ldg(&ts[bi]), 0.001f);
                g_x[0][4 * ni + bi] = make_float4(
                    fmaf(tau, X[i] + bb0, __ldg(&kp[(size_t)p[i] * 3 + 0])),
                    fmaf(tau, Y[i] + bb1, __ldg(&kp[(size_t)p[i] * 3 + 1])),
                    fmaf(tau, Z[i] + bb2, __ldg(&kp[(size_t)p[i] * 3 + 2])), 0.0f);
            }
        }
    }
}

// ---------------------------------------------------------------------------
// Incidence build (side stream, hidden under predict).
// ---------------------------------------------------------------------------
__global__ __launch_bounds__(256) void zero_kernel()
{
    int i = blockIdx.x * blockDim.x + threadIdx.x;
    if (i < Nn) g_cnt[i] = 0;
}

__global__ __launch_bounds__(256) void fill_kernel(
    const int* __restrict__ ei, const float* __restrict__ rest)
{
    int e = blockIdx.x * blockDim.x + threadIdx.x;
    if (e >= En) return;
    int s  = __ldg(&ei[e]);
    int d  = __ldg(&ei[En + e]);
    int L0 = __float_as_int(__ldg(&rest[e]));
    int cs = atomicAdd(&g_cnt[s], 1);
    if (cs < MAXDEG) g_slot[s * MAXDEG + cs] = make_int2(4 * d, L0);
    int cd = atomicAdd(&g_cnt[d], 1);
    if (cd < MAXDEG) g_slot[d * MAXDEG + cd] = make_int2(4 * s, L0);
}

__global__ __launch_bounds__(256) void pad_kernel()
{
    int n = blockIdx.x * blockDim.x + threadIdx.x;
    if (n >= Nn) return;
    int c = min(g_cnt[n], MAXDEG);
    int p = (c + 3) & ~3;                    // pad to multiple of 4
    int2 self = make_int2(4 * n, __float_as_int(1.0f));  // zero contribution
    for (int k = c; k < p; k++) g_slot[n * MAXDEG + k] = self;
    g_cnt[n] = p;
}

// ---------------------------------------------------------------------------
// One XPBD Jacobi iteration. TWO threads per (node, batch): thread half h
// walks 4-edge groups k = 4h, 4h+8, ... (halving the per-thread dependent
// chain), entries for the next group are prefetched before this group's
// gathers (latency overlap). Halves combined with shfl_xor(4); h==0 writes.
// Thread layout t = 8n + 4h + b keeps the 4 batch-siblings' gathers in one
// contiguous 64B segment. 2*NPTS = 400000 threads = 3125 blocks of 128.
// ---------------------------------------------------------------------------
__global__ __launch_bounds__(128) void node_kernel(int from, int to)
{
    int t = blockIdx.x * blockDim.x + threadIdx.x;   // exact: 3125*128
    int n = t >> 3;
    int b = t & 3;
    int h = (t >> 2) & 1;

    const float4* __restrict__ xin = g_x[from];
    float4 own = __ldg(&xin[4 * n + b]);

    int deg = __ldg(&g_cnt[n]);              // multiple of 4
    const int2* row = &g_slot[n * MAXDEG];

    float ax = 0.f, ay = 0.f, az = 0.f;

    int k = 4 * h;
    if (k < deg) {
        int4 ea = __ldg(reinterpret_cast<const int4*>(row + k));
        int4 eb = __ldg(reinterpret_cast<const int4*>(row + k + 2));
        while (true) {
            int kn = k + 8;
            int4 na, nb;
            bool more = (kn < deg);
            if (more) {                      // prefetch next group's entries
                na = __ldg(reinterpret_cast<const int4*>(row + kn));
                nb = __ldg(reinterpret_cast<const int4*>(row + kn + 2));
            }
            int   js[4]  = {ea.x, ea.z, eb.x, eb.z};    // already 4*j
            float L0s[4] = {__int_as_float(ea.y), __int_as_float(ea.w),
                            __int_as_float(eb.y), __int_as_float(eb.w)};
            float4 xj[4];
#pragma unroll
            for (int i = 0; i < 4; i++)
                xj[i] = __ldg(&xin[js[i] + b]);
#pragma unroll
            for (int i = 0; i < 4; i++) {
                float dx = own.x - xj[i].x;
                float dy = own.y - xj[i].y;
                float dz = own.z - xj[i].z;
                float d2 = fmaf(dx, dx, fmaf(dy, dy, dz * dz));
                float r  = rsqrtf(fmaxf(d2, 1e-24f));
                float f  = fmaf(L0s[i], r, -1.0f);      // 2x true scale
                ax += fminf(fmaxf(f * dx, -0.3f), 0.3f);
                ay += fminf(fmaxf(f * dy, -0.3f), 0.3f);
                az += fminf(fmaxf(f * dz, -0.3f), 0.3f);
            }
            if (!more) break;
            ea = na; eb = nb; k = kn;
        }
    }

    // combine the two halves (partner differs only in h -> lane xor 4)
    ax += __shfl_xor_sync(0xffffffffu, ax, 4);
    ay += __shfl_xor_sync(0xffffffffu, ay, 4);
    az += __shfl_xor_sync(0xffffffffu, az, 4);

    if (h == 0)
        g_x[to][4 * n + b] = make_float4(fmaf(0.5f, ax, own.x),
                                         fmaf(0.5f, ay, own.y),
                                         fmaf(0.5f, az, own.z), 0.0f);
}

// ---------------------------------------------------------------------------
// Stage 3: v_eff = (x_corrected - keypoints) / tau
// ---------------------------------------------------------------------------
__global__ __launch_bounds__(256) void final_kernel(
    const float* __restrict__ kp, const float* __restrict__ ts,
    int buf, float* __restrict__ out)
{
    int n = blockIdx.x * blockDim.x + threadIdx.x;
    if (n >= Nn) return;
    const float4* x = g_x[buf];
#pragma unroll
    for (int b = 0; b < Bn; b++) {
        float4 p = x[4 * n + b];
        float inv_tau = 1.0f / fmaxf(1.0f - __ldg(&ts[b]), 0.001f);
        size_t o = (size_t)(b * Nn + n) * 3;
        out[o + 0] = (p.x - __ldg(&kp[o + 0])) * inv_tau;
        out[o + 1] = (p.y - __ldg(&kp[o + 1])) * inv_tau;
        out[o + 2] = (p.z - __ldg(&kp[o + 2])) * inv_tau;
    }
}

extern "C" void kernel_launch(void* const* d_in, const int* in_sizes, int n_in,
                              void* d_out, int out_size)
{
    const float* kp   = (const float*)d_in[0];  // keypoints   (B,N,3)
    const float* ts   = (const float*)d_in[1];  // timesteps   (B,)
    const float* ht   = (const float*)d_in[2];  // hand_tokens (B,N,D)
    const float* hw   = (const float*)d_in[3];  // head_w      (D,3)
    const float* hb   = (const float*)d_in[4];  // head_b      (3,)
    const int*   ei   = (const int*)  d_in[5];  // edge_index  (2,E)
    const float* rest = (const float*)d_in[6];  // rest_lengths(E,)
    float*       out  = (float*)d_out;          // v_eff       (B,N,3)

    (void)in_sizes; (void)n_in; (void)out_size;

    // Side stream + fork/join events, created once on the first (uncaptured)
    // correctness call. Host-side objects only.
    static cudaStream_t side = nullptr;
    static cudaEvent_t  ev_fork = nullptr, ev_join = nullptr;
    if (side == nullptr) {
        cudaStreamCreateWithFlags(&side, cudaStreamNonBlocking);
        cudaEventCreateWithFlags(&ev_fork, cudaEventDisableTiming);
        cudaEventCreateWithFlags(&ev_join, cudaEventDisableTiming);
    }

    const int nb_nodes = (Nn + 255) / 256;
    const int nb_edges = (En + 255) / 256;
    const int nb_node2 = (2 * NPTS) / 128;     // 3125, exact

    // Fork: incidence build on side stream, concurrent with predict.
    cudaEventRecord(ev_fork, 0);
    cudaStreamWaitEvent(side, ev_fork, 0);
    zero_kernel<<<nb_nodes, 256, 0, side>>>();
    fill_kernel<<<nb_edges, 256, 0, side>>>(ei, rest);
    pad_kernel <<<nb_nodes, 256, 0, side>>>();

    // Stage 1 on the main stream, overlapping the build
    predict_kernel<<<PRED_BLOCKS, 256>>>(kp, ts, ht, hw, hb);

    // Join
    cudaEventRecord(ev_join, side);
    cudaStreamWaitEvent(0, ev_join, 0);

    // Stage 2: 4 Jacobi XPBD iterations, node-centric, ping-pong
    node_kernel<<<nb_node2, 128>>>(0, 1);
    node_kernel<<<nb_node2, 128>>>(1, 0);
    node_kernel<<<nb_node2, 128>>>(0, 1);
    node_kernel<<<nb_node2, 128>>>(1, 0);

    // Stage 3: velocity output from buffer 0
    final_kernel<<<nb_nodes, 256>>>(kp, ts, 0, out);
}